// round 1
// baseline (speedup 1.0000x reference)
#include <cuda_runtime.h>
#include <math.h>

// Problem constants (fixed by the reference)
constexpr int Nn = 100000;
constexpr int Ed = 1600000;
constexpr int DIN = 64;

// Scratch (device globals — no allocation allowed)
__device__ float g_agg[(size_t)Nn * 64];
__device__ float g_h0[(size_t)Nn * 64];
__device__ float g_h1[(size_t)Nn * 64];
__device__ float g_logits[(size_t)Nn * 40];
__device__ int   g_deg[Nn];
__device__ float g_invdeg[Nn];

// ---------------------------------------------------------------------------
// Zero agg (and optionally deg). Vectorized float4 stores.
// ---------------------------------------------------------------------------
__global__ void zero_kernel(int also_deg) {
    int i = blockIdx.x * blockDim.x + threadIdx.x;
    if (i < Nn * 16) {
        reinterpret_cast<float4*>(g_agg)[i] = make_float4(0.f, 0.f, 0.f, 0.f);
    }
    if (also_deg && i < Nn) g_deg[i] = 0;
}

// ---------------------------------------------------------------------------
// Degree: one thread per edge
// ---------------------------------------------------------------------------
__global__ void deg_kernel(const int* __restrict__ dst) {
    int e = blockIdx.x * blockDim.x + threadIdx.x;
    if (e < Ed) atomicAdd(&g_deg[dst[e]], 1);
}

__global__ void invdeg_kernel() {
    int i = blockIdx.x * blockDim.x + threadIdx.x;
    if (i < Nn) g_invdeg[i] = 1.0f / fmaxf((float)g_deg[i], 1.0f);
}

// ---------------------------------------------------------------------------
// Scatter-add: 16 threads per edge, each handles one float4 (64 dims total).
// Uses fire-and-forget vectorized L2 reductions (red.global.add.v4.f32).
// ---------------------------------------------------------------------------
__global__ void scatter_kernel(const float* __restrict__ hin,
                               const int* __restrict__ src,
                               const int* __restrict__ dst) {
    int tid = blockIdx.x * blockDim.x + threadIdx.x;
    int e   = tid >> 4;
    int seg = tid & 15;
    if (e >= Ed) return;
    int s = src[e];
    int d = dst[e];
    float4 v = reinterpret_cast<const float4*>(hin + (size_t)s * 64)[seg];
    float* p = g_agg + (size_t)d * 64 + seg * 4;
    asm volatile("red.global.add.v4.f32 [%0], {%1, %2, %3, %4};"
                 :: "l"(p), "f"(v.x), "f"(v.y), "f"(v.z), "f"(v.w)
                 : "memory");
}

// ---------------------------------------------------------------------------
// Transform: out[n] = (agg[n]*invdeg[n]) @ Wl + bl + hin[n] @ Wr  (+ReLU)
// Block: 64 threads (out dim) x NPB nodes. Weights staged in shared.
// ---------------------------------------------------------------------------
template <int DOUT, bool RELU>
__global__ void transform_kernel(const float* __restrict__ hin,
                                 const float* __restrict__ Wl,
                                 const float* __restrict__ bl,
                                 const float* __restrict__ Wr,
                                 float* __restrict__ out) {
    constexpr int NPB = 4;
    __shared__ float sWl[DIN * DOUT];
    __shared__ float sWr[DIN * DOUT];
    __shared__ float sA[NPB][DIN];
    __shared__ float sH[NPB][DIN];

    int tx = threadIdx.x;            // 0..63
    int ty = threadIdx.y;            // 0..NPB-1
    int tid = ty * 64 + tx;

    for (int i = tid; i < DIN * DOUT; i += 64 * NPB) {
        sWl[i] = Wl[i];
        sWr[i] = Wr[i];
    }

    int n = blockIdx.x * NPB + ty;
    if (n < Nn) {
        float invd = g_invdeg[n];
        sA[ty][tx] = g_agg[(size_t)n * 64 + tx] * invd;
        sH[ty][tx] = hin[(size_t)n * 64 + tx];
    }
    __syncthreads();

    if (n < Nn && tx < DOUT) {
        float acc = bl[tx];
#pragma unroll
        for (int k = 0; k < DIN; k++) {
            acc = fmaf(sA[ty][k], sWl[k * DOUT + tx], acc);
            acc = fmaf(sH[ty][k], sWr[k * DOUT + tx], acc);
        }
        if (RELU) acc = fmaxf(acc, 0.0f);
        out[(size_t)n * DOUT + tx] = acc;
    }
}

// ---------------------------------------------------------------------------
// log_softmax over 40 classes: one warp per node.
// lane covers dim=lane (always <40 for lane<32) and dim=32+lane (lane<8).
// ---------------------------------------------------------------------------
__global__ void logsoftmax_kernel(float* __restrict__ out) {
    int gtid = blockIdx.x * blockDim.x + threadIdx.x;
    int node = gtid >> 5;
    int lane = gtid & 31;
    if (node >= Nn) return;
    const float* row = g_logits + (size_t)node * 40;

    float v0 = row[lane];
    float v1 = (lane < 8) ? row[32 + lane] : -INFINITY;

    float m = fmaxf(v0, v1);
#pragma unroll
    for (int o = 16; o; o >>= 1) m = fmaxf(m, __shfl_xor_sync(0xFFFFFFFFu, m, o));

    float s = expf(v0 - m) + ((lane < 8) ? expf(v1 - m) : 0.0f);
#pragma unroll
    for (int o = 16; o; o >>= 1) s += __shfl_xor_sync(0xFFFFFFFFu, s, o);

    float lse = m + logf(s);
    out[(size_t)node * 40 + lane] = v0 - lse;
    if (lane < 8) out[(size_t)node * 40 + 32 + lane] = v1 - lse;
}

// ---------------------------------------------------------------------------
// Launcher
// ---------------------------------------------------------------------------
extern "C" void kernel_launch(void* const* d_in, const int* in_sizes, int n_in,
                              void* d_out, int out_size) {
    const float* x   = (const float*)d_in[0];
    const int*   ei  = (const int*)d_in[1];
    const int*   src = ei;
    const int*   dst = ei + Ed;
    const float* Wl0 = (const float*)d_in[2];
    const float* bl0 = (const float*)d_in[3];
    const float* Wr0 = (const float*)d_in[4];
    const float* Wl1 = (const float*)d_in[5];
    const float* bl1 = (const float*)d_in[6];
    const float* Wr1 = (const float*)d_in[7];
    const float* Wl2 = (const float*)d_in[8];
    const float* bl2 = (const float*)d_in[9];
    const float* Wr2 = (const float*)d_in[10];
    float* out = (float*)d_out;

    float *h0p, *h1p, *logitsp;
    cudaGetSymbolAddress((void**)&h0p, g_h0);
    cudaGetSymbolAddress((void**)&h1p, g_h1);
    cudaGetSymbolAddress((void**)&logitsp, g_logits);

    const int ZB = 256;
    const int zgrid = (Nn * 16 + ZB - 1) / ZB;
    const int egrid = (Ed + 255) / 256;
    const int sgrid = (Ed * 16 + 255) / 256;
    const int ngrid = (Nn + 255) / 256;
    dim3 tblk(64, 4);
    const int tgrid = (Nn + 3) / 4;
    const int lsgrid = (Nn * 32 + 255) / 256;

    // Degree (once) + zero agg
    zero_kernel<<<zgrid, ZB>>>(1);
    deg_kernel<<<egrid, 256>>>(dst);
    invdeg_kernel<<<ngrid, 256>>>();

    // Layer 0: x -> h0
    scatter_kernel<<<sgrid, 256>>>(x, src, dst);
    transform_kernel<64, true><<<tgrid, tblk>>>(x, Wl0, bl0, Wr0, h0p);

    // Layer 1: h0 -> h1
    zero_kernel<<<zgrid, ZB>>>(0);
    scatter_kernel<<<sgrid, 256>>>(h0p, src, dst);
    transform_kernel<64, true><<<tgrid, tblk>>>(h0p, Wl1, bl1, Wr1, h1p);

    // Layer 2: h1 -> logits
    zero_kernel<<<zgrid, ZB>>>(0);
    scatter_kernel<<<sgrid, 256>>>(h1p, src, dst);
    transform_kernel<40, false><<<tgrid, tblk>>>(h1p, Wl2, bl2, Wr2, logitsp);

    // log_softmax -> out
    logsoftmax_kernel<<<lsgrid, 256>>>(out);
}

// round 2
// speedup vs baseline: 1.7431x; 1.7431x over previous
#include <cuda_runtime.h>
#include <math.h>

constexpr int Nn = 100000;
constexpr int Ed = 1600000;
constexpr int DIN = 64;
constexpr int NB_SCAN = (Nn + 1023) / 1024;   // 98

// ---- scratch (device globals; no allocation allowed) ----------------------
__device__ float g_y[(size_t)Nn * 64];        // h @ Wl
__device__ float g_p[(size_t)Nn * 64];        // h @ Wr + bl
__device__ float g_h0[(size_t)Nn * 64];
__device__ float g_h1[(size_t)Nn * 64];
__device__ int   g_csr_src[Ed];
__device__ int   g_rowptr[Nn];
__device__ int   g_rowloc[Nn];
__device__ int   g_cursor[Nn];
__device__ int   g_deg[Nn];
__device__ float g_invdeg[Nn];
__device__ int   g_bsum[NB_SCAN];
__device__ int   g_bsumx[128];

// ---------------------------------------------------------------------------
__global__ void zero_deg_kernel() {
    int i = blockIdx.x * blockDim.x + threadIdx.x;
    if (i < Nn) g_deg[i] = 0;
}

__global__ void deg_kernel(const int* __restrict__ dst) {
    int e = blockIdx.x * blockDim.x + threadIdx.x;
    if (e < Ed) atomicAdd(&g_deg[dst[e]], 1);
}

__global__ void invdeg_kernel() {
    int i = blockIdx.x * blockDim.x + threadIdx.x;
    if (i < Nn) g_invdeg[i] = 1.0f / fmaxf((float)g_deg[i], 1.0f);
}

// ---- two-level exclusive scan of degrees -> rowptr ------------------------
__global__ void scanA_kernel() {
    __shared__ int sh[1024];
    int tid = threadIdx.x;
    int i = blockIdx.x * 1024 + tid;
    int v = (i < Nn) ? g_deg[i] : 0;
    sh[tid] = v;
    __syncthreads();
#pragma unroll
    for (int off = 1; off < 1024; off <<= 1) {
        int t = (tid >= off) ? sh[tid - off] : 0;
        __syncthreads();
        sh[tid] += t;
        __syncthreads();
    }
    if (i < Nn) g_rowloc[i] = sh[tid] - v;          // exclusive within block
    if (tid == 1023) g_bsum[blockIdx.x] = sh[1023]; // block total
}

__global__ void scanB_kernel() {
    __shared__ int sh[128];
    int tid = threadIdx.x;
    int v = (tid < NB_SCAN) ? g_bsum[tid] : 0;
    sh[tid] = v;
    __syncthreads();
#pragma unroll
    for (int off = 1; off < 128; off <<= 1) {
        int t = (tid >= off) ? sh[tid - off] : 0;
        __syncthreads();
        sh[tid] += t;
        __syncthreads();
    }
    g_bsumx[tid] = sh[tid] - v;                     // exclusive block offsets
}

__global__ void scanC_kernel() {
    int i = blockIdx.x * blockDim.x + threadIdx.x;
    if (i < Nn) {
        int r = g_rowloc[i] + g_bsumx[i >> 10];
        g_rowptr[i] = r;
        g_cursor[i] = r;
    }
}

__global__ void fill_kernel(const int* __restrict__ src,
                            const int* __restrict__ dst) {
    int e = blockIdx.x * blockDim.x + threadIdx.x;
    if (e < Ed) {
        int pos = atomicAdd(&g_cursor[dst[e]], 1);
        g_csr_src[pos] = src[e];
    }
}

// ---------------------------------------------------------------------------
// Transform: y = h @ Wl ; p = h @ Wr + bl.
// Block = (32, 8): tx covers DOUT in float2 pairs, ty = node within tile.
// Weights staged once per block; block grid-strides over node tiles.
// ---------------------------------------------------------------------------
template <int DOUT>
__global__ void transform_kernel(const float* __restrict__ hin,
                                 const float* __restrict__ Wl,
                                 const float* __restrict__ bl,
                                 const float* __restrict__ Wr,
                                 float* __restrict__ y,
                                 float* __restrict__ p) {
    __shared__ float sWl[DIN * 64];   // padded to 64 cols (idle lanes harmless)
    __shared__ float sWr[DIN * 64];
    __shared__ float sbl[64];
    __shared__ float sH[8][DIN];

    int tx = threadIdx.x;             // 0..31
    int ty = threadIdx.y;             // 0..7
    int tid = ty * 32 + tx;
    const bool act = (2 * tx) < DOUT;

    for (int i = tid; i < DIN * DOUT; i += 256) {
        sWl[i] = Wl[i];
        sWr[i] = Wr[i];
    }
    if (tid < DOUT) sbl[tid] = bl[tid];
    __syncthreads();

    const int ntiles = (Nn + 7) / 8;
    for (int tile = blockIdx.x; tile < ntiles; tile += gridDim.x) {
        int n = tile * 8 + ty;
        if (n < Nn) {
            float2 hv = *reinterpret_cast<const float2*>(hin + (size_t)n * DIN + 2 * tx);
            sH[ty][2 * tx]     = hv.x;
            sH[ty][2 * tx + 1] = hv.y;
        }
        __syncthreads();

        if (n < Nn && act) {
            float2 al = make_float2(0.f, 0.f);
            float2 ar = make_float2(sbl[2 * tx], sbl[2 * tx + 1]);
#pragma unroll
            for (int k = 0; k < DIN; k++) {
                float h = sH[ty][k];
                float2 wl = *reinterpret_cast<const float2*>(&sWl[k * DOUT + 2 * tx]);
                float2 wr = *reinterpret_cast<const float2*>(&sWr[k * DOUT + 2 * tx]);
                al.x = fmaf(h, wl.x, al.x);
                al.y = fmaf(h, wl.y, al.y);
                ar.x = fmaf(h, wr.x, ar.x);
                ar.y = fmaf(h, wr.y, ar.y);
            }
            *reinterpret_cast<float2*>(y + (size_t)n * DOUT + 2 * tx) = al;
            *reinterpret_cast<float2*>(p + (size_t)n * DOUT + 2 * tx) = ar;
        }
        __syncthreads();
    }
}

// ---------------------------------------------------------------------------
// Gather: out[n] = act( invdeg[n] * sum_{j in N(n)} y[j] + p[n] )
// Warp per node; lane covers dims [2*lane, 2*lane+1] as float2.
// FINAL=true additionally applies log_softmax across the 40-dim row.
// ---------------------------------------------------------------------------
template <int DOUT, bool RELU, bool FINAL>
__global__ void gather_kernel(const float* __restrict__ y,
                              const float* __restrict__ p,
                              float* __restrict__ out) {
    int w = (blockIdx.x * blockDim.x + threadIdx.x) >> 5;
    int lane = threadIdx.x & 31;
    if (w >= Nn) return;
    const bool act = (2 * lane) < DOUT;

    int start = g_rowptr[w];
    int cnt   = g_deg[w];
    float2 acc = make_float2(0.f, 0.f);

    for (int base = 0; base < cnt; base += 32) {
        int rem = cnt - base;
        int idx = 0;
        if (lane < rem) idx = g_csr_src[start + base + lane];
        int lim = rem < 32 ? rem : 32;
        for (int t = 0; t < lim; t++) {
            int s = __shfl_sync(0xFFFFFFFFu, idx, t);
            if (act) {
                float2 v = *reinterpret_cast<const float2*>(y + (size_t)s * DOUT + 2 * lane);
                acc.x += v.x;
                acc.y += v.y;
            }
        }
    }

    float invd = g_invdeg[w];
    float2 o = make_float2(0.f, 0.f);
    if (act) {
        float2 pp = *reinterpret_cast<const float2*>(p + (size_t)w * DOUT + 2 * lane);
        o.x = fmaf(acc.x, invd, pp.x);
        o.y = fmaf(acc.y, invd, pp.y);
        if (RELU) { o.x = fmaxf(o.x, 0.f); o.y = fmaxf(o.y, 0.f); }
    }

    if (FINAL) {
        float m = act ? fmaxf(o.x, o.y) : -INFINITY;
#pragma unroll
        for (int off = 16; off; off >>= 1) m = fmaxf(m, __shfl_xor_sync(0xFFFFFFFFu, m, off));
        float s = act ? (expf(o.x - m) + expf(o.y - m)) : 0.f;
#pragma unroll
        for (int off = 16; off; off >>= 1) s += __shfl_xor_sync(0xFFFFFFFFu, s, off);
        float lse = m + logf(s);
        o.x -= lse;
        o.y -= lse;
    }
    if (act)
        *reinterpret_cast<float2*>(out + (size_t)w * DOUT + 2 * lane) = o;
}

// ---------------------------------------------------------------------------
extern "C" void kernel_launch(void* const* d_in, const int* in_sizes, int n_in,
                              void* d_out, int out_size) {
    const float* x   = (const float*)d_in[0];
    const int*   ei  = (const int*)d_in[1];
    const int*   src = ei;
    const int*   dst = ei + Ed;
    const float* Wl0 = (const float*)d_in[2];
    const float* bl0 = (const float*)d_in[3];
    const float* Wr0 = (const float*)d_in[4];
    const float* Wl1 = (const float*)d_in[5];
    const float* bl1 = (const float*)d_in[6];
    const float* Wr1 = (const float*)d_in[7];
    const float* Wl2 = (const float*)d_in[8];
    const float* bl2 = (const float*)d_in[9];
    const float* Wr2 = (const float*)d_in[10];
    float* out = (float*)d_out;

    float *yp, *pp, *h0p, *h1p;
    cudaGetSymbolAddress((void**)&yp,  g_y);
    cudaGetSymbolAddress((void**)&pp,  g_p);
    cudaGetSymbolAddress((void**)&h0p, g_h0);
    cudaGetSymbolAddress((void**)&h1p, g_h1);

    const int ngrid = (Nn + 255) / 256;
    const int egrid = (Ed + 255) / 256;
    const int ggrid = (Nn * 32 + 255) / 256;    // warp per node
    dim3 tblk(32, 8);
    const int tgrid = 888;                      // 148 SMs * 6 blocks

    // ---- CSR build (once per call, reused for all 3 layers) ----
    zero_deg_kernel<<<ngrid, 256>>>();
    deg_kernel<<<egrid, 256>>>(dst);
    invdeg_kernel<<<ngrid, 256>>>();
    scanA_kernel<<<NB_SCAN, 1024>>>();
    scanB_kernel<<<1, 128>>>();
    scanC_kernel<<<ngrid, 256>>>();
    fill_kernel<<<egrid, 256>>>(src, dst);

    // ---- Layer 0: x -> h0 ----
    transform_kernel<64><<<tgrid, tblk>>>(x, Wl0, bl0, Wr0, yp, pp);
    gather_kernel<64, true, false><<<ggrid, 256>>>(yp, pp, h0p);

    // ---- Layer 1: h0 -> h1 ----
    transform_kernel<64><<<tgrid, tblk>>>(h0p, Wl1, bl1, Wr1, yp, pp);
    gather_kernel<64, true, false><<<ggrid, 256>>>(yp, pp, h1p);

    // ---- Layer 2: h1 -> out (gather fused with log_softmax) ----
    transform_kernel<40><<<tgrid, tblk>>>(h1p, Wl2, bl2, Wr2, yp, pp);
    gather_kernel<40, false, true><<<ggrid, 256>>>(yp, pp, out);
}

// round 3
// speedup vs baseline: 1.7986x; 1.0318x over previous
#include <cuda_runtime.h>
#include <cuda_fp16.h>
#include <math.h>

constexpr int Nn = 100000;
constexpr int Ed = 1600000;
constexpr int DIN = 64;
constexpr int NB_SCAN = (Nn + 1023) / 1024;   // 98

// ---- scratch (device globals; no allocation allowed) ----------------------
__device__ __half g_y[(size_t)Nn * 64];       // h @ Wl   (fp16)
__device__ float  g_p[(size_t)Nn * 64];       // h @ Wr + bl (fp32)
__device__ float  g_h0[(size_t)Nn * 64];
__device__ float  g_h1[(size_t)Nn * 64];
__device__ int    g_csr_src[Ed];
__device__ int    g_rowptr[Nn];
__device__ int    g_rowloc[Nn];
__device__ int    g_cursor[Nn];
__device__ int    g_deg[Nn];
__device__ float  g_invdeg[Nn];
__device__ int    g_bsum[NB_SCAN];
__device__ int    g_bsumx[128];

// ---------------------------------------------------------------------------
__global__ void zero_deg_kernel() {
    int i = blockIdx.x * blockDim.x + threadIdx.x;
    if (i < Nn) g_deg[i] = 0;
}

__global__ void deg_kernel(const int* __restrict__ dst) {
    int e = blockIdx.x * blockDim.x + threadIdx.x;
    if (e < Ed) atomicAdd(&g_deg[__ldg(dst + e)], 1);
}

// ---- two-level exclusive scan of degrees -> rowptr (+ invdeg fused) -------
__global__ void scanA_kernel() {
    __shared__ int sh[1024];
    int tid = threadIdx.x;
    int i = blockIdx.x * 1024 + tid;
    int v = (i < Nn) ? g_deg[i] : 0;
    if (i < Nn) g_invdeg[i] = 1.0f / fmaxf((float)v, 1.0f);
    sh[tid] = v;
    __syncthreads();
#pragma unroll
    for (int off = 1; off < 1024; off <<= 1) {
        int t = (tid >= off) ? sh[tid - off] : 0;
        __syncthreads();
        sh[tid] += t;
        __syncthreads();
    }
    if (i < Nn) g_rowloc[i] = sh[tid] - v;          // exclusive within block
    if (tid == 1023) g_bsum[blockIdx.x] = sh[1023]; // block total
}

__global__ void scanB_kernel() {
    __shared__ int sh[128];
    int tid = threadIdx.x;
    int v = (tid < NB_SCAN) ? g_bsum[tid] : 0;
    sh[tid] = v;
    __syncthreads();
#pragma unroll
    for (int off = 1; off < 128; off <<= 1) {
        int t = (tid >= off) ? sh[tid - off] : 0;
        __syncthreads();
        sh[tid] += t;
        __syncthreads();
    }
    g_bsumx[tid] = sh[tid] - v;                     // exclusive block offsets
}

__global__ void scanC_kernel() {
    int i = blockIdx.x * blockDim.x + threadIdx.x;
    if (i < Nn) {
        int r = g_rowloc[i] + g_bsumx[i >> 10];
        g_rowptr[i] = r;
        g_cursor[i] = r;
    }
}

__global__ void fill_kernel(const int* __restrict__ src,
                            const int* __restrict__ dst) {
    int e = blockIdx.x * blockDim.x + threadIdx.x;
    if (e < Ed) {
        int pos = atomicAdd(&g_cursor[__ldg(dst + e)], 1);
        g_csr_src[pos] = __ldg(src + e);
    }
}

// ---------------------------------------------------------------------------
// Transform: y = h @ Wl (-> fp16) ; p = h @ Wr + bl (fp32).
// Block = (32, 8): tx covers DOUT in pairs, ty = node within tile.
// Weights staged once per block; block grid-strides over node tiles.
// ---------------------------------------------------------------------------
template <int DOUT>
__global__ void transform_kernel(const float* __restrict__ hin,
                                 const float* __restrict__ Wl,
                                 const float* __restrict__ bl,
                                 const float* __restrict__ Wr,
                                 __half* __restrict__ y,
                                 float* __restrict__ p) {
    __shared__ float sWl[DIN * 64];
    __shared__ float sWr[DIN * 64];
    __shared__ float sbl[64];
    __shared__ float sH[8][DIN];

    int tx = threadIdx.x;             // 0..31
    int ty = threadIdx.y;             // 0..7
    int tid = ty * 32 + tx;
    const bool act = (2 * tx) < DOUT;

    for (int i = tid; i < DIN * DOUT; i += 256) {
        sWl[i] = Wl[i];
        sWr[i] = Wr[i];
    }
    if (tid < DOUT) sbl[tid] = bl[tid];
    __syncthreads();

    const int ntiles = (Nn + 7) / 8;
    for (int tile = blockIdx.x; tile < ntiles; tile += gridDim.x) {
        int n = tile * 8 + ty;
        if (n < Nn) {
            float2 hv = *reinterpret_cast<const float2*>(hin + (size_t)n * DIN + 2 * tx);
            sH[ty][2 * tx]     = hv.x;
            sH[ty][2 * tx + 1] = hv.y;
        }
        __syncthreads();

        if (n < Nn && act) {
            float2 al = make_float2(0.f, 0.f);
            float2 ar = make_float2(sbl[2 * tx], sbl[2 * tx + 1]);
#pragma unroll
            for (int k = 0; k < DIN; k++) {
                float h = sH[ty][k];
                float2 wl = *reinterpret_cast<const float2*>(&sWl[k * DOUT + 2 * tx]);
                float2 wr = *reinterpret_cast<const float2*>(&sWr[k * DOUT + 2 * tx]);
                al.x = fmaf(h, wl.x, al.x);
                al.y = fmaf(h, wl.y, al.y);
                ar.x = fmaf(h, wr.x, ar.x);
                ar.y = fmaf(h, wr.y, ar.y);
            }
            reinterpret_cast<__half2*>(y + (size_t)n * DOUT)[tx] = __float22half2_rn(al);
            *reinterpret_cast<float2*>(p + (size_t)n * DOUT + 2 * tx) = ar;
        }
        __syncthreads();
    }
}

// ---------------------------------------------------------------------------
// Gather: out[n] = act( invdeg[n] * sum_{j in N(n)} y[j] + p[n] )
// Warp per node; lane covers dims [2*lane, 2*lane+1]; y rows read as half2.
// FINAL=true additionally applies log_softmax across the 40-dim row.
// ---------------------------------------------------------------------------
template <int DOUT, bool RELU, bool FINAL>
__global__ void gather_kernel(const __half* __restrict__ y,
                              const float* __restrict__ p,
                              float* __restrict__ out) {
    int w = (blockIdx.x * blockDim.x + threadIdx.x) >> 5;
    int lane = threadIdx.x & 31;
    if (w >= Nn) return;
    const bool act = (2 * lane) < DOUT;

    int start = g_rowptr[w];
    int cnt   = g_deg[w];
    float2 acc = make_float2(0.f, 0.f);

    for (int base = 0; base < cnt; base += 32) {
        int rem = cnt - base;
        int idx = 0;
        if (lane < rem) idx = g_csr_src[start + base + lane];
        int lim = rem < 32 ? rem : 32;
        for (int t = 0; t < lim; t++) {
            int s = __shfl_sync(0xFFFFFFFFu, idx, t);
            if (act) {
                __half2 v = reinterpret_cast<const __half2*>(y + (size_t)s * DOUT)[lane];
                float2 vf = __half22float2(v);
                acc.x += vf.x;
                acc.y += vf.y;
            }
        }
    }

    float invd = g_invdeg[w];
    float2 o = make_float2(0.f, 0.f);
    if (act) {
        float2 pp = *reinterpret_cast<const float2*>(p + (size_t)w * DOUT + 2 * lane);
        o.x = fmaf(acc.x, invd, pp.x);
        o.y = fmaf(acc.y, invd, pp.y);
        if (RELU) { o.x = fmaxf(o.x, 0.f); o.y = fmaxf(o.y, 0.f); }
    }

    if (FINAL) {
        float m = act ? fmaxf(o.x, o.y) : -INFINITY;
#pragma unroll
        for (int off = 16; off; off >>= 1) m = fmaxf(m, __shfl_xor_sync(0xFFFFFFFFu, m, off));
        float s = act ? (expf(o.x - m) + expf(o.y - m)) : 0.f;
#pragma unroll
        for (int off = 16; off; off >>= 1) s += __shfl_xor_sync(0xFFFFFFFFu, s, off);
        float lse = m + logf(s);
        o.x -= lse;
        o.y -= lse;
    }
    if (act)
        *reinterpret_cast<float2*>(out + (size_t)w * DOUT + 2 * lane) = o;
}

// ---------------------------------------------------------------------------
extern "C" void kernel_launch(void* const* d_in, const int* in_sizes, int n_in,
                              void* d_out, int out_size) {
    const float* x   = (const float*)d_in[0];
    const int*   ei  = (const int*)d_in[1];
    const int*   src = ei;
    const int*   dst = ei + Ed;
    const float* Wl0 = (const float*)d_in[2];
    const float* bl0 = (const float*)d_in[3];
    const float* Wr0 = (const float*)d_in[4];
    const float* Wl1 = (const float*)d_in[5];
    const float* bl1 = (const float*)d_in[6];
    const float* Wr1 = (const float*)d_in[7];
    const float* Wl2 = (const float*)d_in[8];
    const float* bl2 = (const float*)d_in[9];
    const float* Wr2 = (const float*)d_in[10];
    float* out = (float*)d_out;

    __half* yp;
    float *pp, *h0p, *h1p;
    cudaGetSymbolAddress((void**)&yp,  g_y);
    cudaGetSymbolAddress((void**)&pp,  g_p);
    cudaGetSymbolAddress((void**)&h0p, g_h0);
    cudaGetSymbolAddress((void**)&h1p, g_h1);

    const int ngrid = (Nn + 255) / 256;
    const int egrid = (Ed + 255) / 256;
    const int ggrid = (Nn * 32 + 255) / 256;    // warp per node
    dim3 tblk(32, 8);
    const int tgrid = 888;                      // ~6 blocks/SM

    // ---- CSR build (once per call, reused for all 3 layers) ----
    zero_deg_kernel<<<ngrid, 256>>>();
    deg_kernel<<<egrid, 256>>>(dst);
    scanA_kernel<<<NB_SCAN, 1024>>>();
    scanB_kernel<<<1, 128>>>();
    scanC_kernel<<<ngrid, 256>>>();
    fill_kernel<<<egrid, 256>>>(src, dst);

    // ---- Layer 0: x -> h0 ----
    transform_kernel<64><<<tgrid, tblk>>>(x, Wl0, bl0, Wr0, yp, pp);
    gather_kernel<64, true, false><<<ggrid, 256>>>(yp, pp, h0p);

    // ---- Layer 1: h0 -> h1 ----
    transform_kernel<64><<<tgrid, tblk>>>(h0p, Wl1, bl1, Wr1, yp, pp);
    gather_kernel<64, true, false><<<ggrid, 256>>>(yp, pp, h1p);

    // ---- Layer 2: h1 -> out (gather fused with log_softmax) ----
    transform_kernel<40><<<tgrid, tblk>>>(h1p, Wl2, bl2, Wr2, yp, pp);
    gather_kernel<40, false, true><<<ggrid, 256>>>(yp, pp, out);
}

// round 4
// speedup vs baseline: 1.8713x; 1.0404x over previous
#include <cuda_runtime.h>
#include <cuda_fp16.h>
#include <math.h>

constexpr int Nn = 100000;
constexpr int Ed = 1600000;
constexpr int DIN = 64;
constexpr int NB_SCAN = (Nn + 1023) / 1024;   // 98

// ---- scratch (device globals; no allocation allowed) ----------------------
__device__ __half g_y[(size_t)Nn * 64];       // h @ Wl   (fp16)
__device__ float  g_p[(size_t)Nn * 64];       // h @ Wr + bl (fp32)
__device__ float  g_h0[(size_t)Nn * 64];
__device__ float  g_h1[(size_t)Nn * 64];
__device__ int    g_csr_src[Ed];
__device__ int    g_rowptr[Nn];
__device__ int    g_rowloc[Nn];
__device__ int    g_cursor[Nn];
__device__ int    g_deg[Nn];
__device__ float  g_invdeg[Nn];
__device__ int    g_bsum[NB_SCAN];
__device__ int    g_bsumx[128];

// ---------------------------------------------------------------------------
__global__ void zero_deg_kernel() {
    int i = blockIdx.x * blockDim.x + threadIdx.x;
    if (i < Nn) g_deg[i] = 0;
}

__global__ void deg_kernel(const int* __restrict__ dst) {
    int e = blockIdx.x * blockDim.x + threadIdx.x;
    if (e < Ed) atomicAdd(&g_deg[__ldg(dst + e)], 1);
}

// ---- two-level exclusive scan of degrees -> rowptr (+ invdeg fused) -------
__global__ void scanA_kernel() {
    __shared__ int sh[1024];
    int tid = threadIdx.x;
    int i = blockIdx.x * 1024 + tid;
    int v = (i < Nn) ? g_deg[i] : 0;
    if (i < Nn) g_invdeg[i] = 1.0f / fmaxf((float)v, 1.0f);
    sh[tid] = v;
    __syncthreads();
#pragma unroll
    for (int off = 1; off < 1024; off <<= 1) {
        int t = (tid >= off) ? sh[tid - off] : 0;
        __syncthreads();
        sh[tid] += t;
        __syncthreads();
    }
    if (i < Nn) g_rowloc[i] = sh[tid] - v;          // exclusive within block
    if (tid == 1023) g_bsum[blockIdx.x] = sh[1023]; // block total
}

__global__ void scanB_kernel() {
    __shared__ int sh[128];
    int tid = threadIdx.x;
    int v = (tid < NB_SCAN) ? g_bsum[tid] : 0;
    sh[tid] = v;
    __syncthreads();
#pragma unroll
    for (int off = 1; off < 128; off <<= 1) {
        int t = (tid >= off) ? sh[tid - off] : 0;
        __syncthreads();
        sh[tid] += t;
        __syncthreads();
    }
    g_bsumx[tid] = sh[tid] - v;                     // exclusive block offsets
}

__global__ void scanC_kernel() {
    int i = blockIdx.x * blockDim.x + threadIdx.x;
    if (i < Nn) {
        int r = g_rowloc[i] + g_bsumx[i >> 10];
        g_rowptr[i] = r;
        g_cursor[i] = r;
    }
}

__global__ void fill_kernel(const int* __restrict__ src,
                            const int* __restrict__ dst) {
    int e = blockIdx.x * blockDim.x + threadIdx.x;
    if (e < Ed) {
        int pos = atomicAdd(&g_cursor[__ldg(dst + e)], 1);
        g_csr_src[pos] = __ldg(src + e);
    }
}

// ---------------------------------------------------------------------------
// Transform: y = h @ Wl (-> fp16) ; p = h @ Wr + bl (fp32).
// ---------------------------------------------------------------------------
template <int DOUT>
__global__ void transform_kernel(const float* __restrict__ hin,
                                 const float* __restrict__ Wl,
                                 const float* __restrict__ bl,
                                 const float* __restrict__ Wr,
                                 __half* __restrict__ y,
                                 float* __restrict__ p) {
    __shared__ float sWl[DIN * 64];
    __shared__ float sWr[DIN * 64];
    __shared__ float sbl[64];
    __shared__ float sH[8][DIN];

    int tx = threadIdx.x;             // 0..31
    int ty = threadIdx.y;             // 0..7
    int tid = ty * 32 + tx;
    const bool act = (2 * tx) < DOUT;

    for (int i = tid; i < DIN * DOUT; i += 256) {
        sWl[i] = Wl[i];
        sWr[i] = Wr[i];
    }
    if (tid < DOUT) sbl[tid] = bl[tid];
    __syncthreads();

    const int ntiles = (Nn + 7) / 8;
    for (int tile = blockIdx.x; tile < ntiles; tile += gridDim.x) {
        int n = tile * 8 + ty;
        if (n < Nn) {
            float2 hv = *reinterpret_cast<const float2*>(hin + (size_t)n * DIN + 2 * tx);
            sH[ty][2 * tx]     = hv.x;
            sH[ty][2 * tx + 1] = hv.y;
        }
        __syncthreads();

        if (n < Nn && act) {
            float2 al = make_float2(0.f, 0.f);
            float2 ar = make_float2(sbl[2 * tx], sbl[2 * tx + 1]);
#pragma unroll
            for (int k = 0; k < DIN; k++) {
                float h = sH[ty][k];
                float2 wl = *reinterpret_cast<const float2*>(&sWl[k * DOUT + 2 * tx]);
                float2 wr = *reinterpret_cast<const float2*>(&sWr[k * DOUT + 2 * tx]);
                al.x = fmaf(h, wl.x, al.x);
                al.y = fmaf(h, wl.y, al.y);
                ar.x = fmaf(h, wr.x, ar.x);
                ar.y = fmaf(h, wr.y, ar.y);
            }
            reinterpret_cast<__half2*>(y + (size_t)n * DOUT)[tx] = __float22half2_rn(al);
            *reinterpret_cast<float2*>(p + (size_t)n * DOUT + 2 * tx) = ar;
        }
        __syncthreads();
    }
}

// ---------------------------------------------------------------------------
// Gather: out[n] = act( invdeg[n] * sum_{j in N(n)} y[j] + p[n] )
// Warp per node; lane covers one half2 (dims 2*lane..2*lane+1).
// Inner loop unrolled x8 with broadcast index loads (no shfl) -> MLP=8.
// ---------------------------------------------------------------------------
template <int DOUT, bool RELU, bool FINAL>
__global__ void gather_kernel(const __half* __restrict__ y,
                              const float* __restrict__ p,
                              float* __restrict__ out) {
    int w = (blockIdx.x * blockDim.x + threadIdx.x) >> 5;
    int lane = threadIdx.x & 31;
    if (w >= Nn) return;
    const bool act = (2 * lane) < DOUT;

    const int start = g_rowptr[w];
    const int cnt   = g_deg[w];
    const int* __restrict__ idxp = g_csr_src + start;
    const __half2* __restrict__ y2 = reinterpret_cast<const __half2*>(y);
    constexpr int STRIDE = DOUT / 2;   // half2 per row

    float2 acc = make_float2(0.f, 0.f);
    int i = 0;
    for (; i + 8 <= cnt; i += 8) {
        int s0 = __ldg(idxp + i + 0);
        int s1 = __ldg(idxp + i + 1);
        int s2 = __ldg(idxp + i + 2);
        int s3 = __ldg(idxp + i + 3);
        int s4 = __ldg(idxp + i + 4);
        int s5 = __ldg(idxp + i + 5);
        int s6 = __ldg(idxp + i + 6);
        int s7 = __ldg(idxp + i + 7);
        if (act) {
            __half2 v0 = __ldg(y2 + (size_t)s0 * STRIDE + lane);
            __half2 v1 = __ldg(y2 + (size_t)s1 * STRIDE + lane);
            __half2 v2 = __ldg(y2 + (size_t)s2 * STRIDE + lane);
            __half2 v3 = __ldg(y2 + (size_t)s3 * STRIDE + lane);
            __half2 v4 = __ldg(y2 + (size_t)s4 * STRIDE + lane);
            __half2 v5 = __ldg(y2 + (size_t)s5 * STRIDE + lane);
            __half2 v6 = __ldg(y2 + (size_t)s6 * STRIDE + lane);
            __half2 v7 = __ldg(y2 + (size_t)s7 * STRIDE + lane);
            float2 f0 = __half22float2(v0), f1 = __half22float2(v1);
            float2 f2 = __half22float2(v2), f3 = __half22float2(v3);
            float2 f4 = __half22float2(v4), f5 = __half22float2(v5);
            float2 f6 = __half22float2(v6), f7 = __half22float2(v7);
            acc.x += ((f0.x + f1.x) + (f2.x + f3.x)) + ((f4.x + f5.x) + (f6.x + f7.x));
            acc.y += ((f0.y + f1.y) + (f2.y + f3.y)) + ((f4.y + f5.y) + (f6.y + f7.y));
        }
    }
    for (; i < cnt; i++) {
        int s = __ldg(idxp + i);
        if (act) {
            float2 f = __half22float2(__ldg(y2 + (size_t)s * STRIDE + lane));
            acc.x += f.x;
            acc.y += f.y;
        }
    }

    float invd = g_invdeg[w];
    float2 o = make_float2(0.f, 0.f);
    if (act) {
        float2 pp = *reinterpret_cast<const float2*>(p + (size_t)w * DOUT + 2 * lane);
        o.x = fmaf(acc.x, invd, pp.x);
        o.y = fmaf(acc.y, invd, pp.y);
        if (RELU) { o.x = fmaxf(o.x, 0.f); o.y = fmaxf(o.y, 0.f); }
    }

    if (FINAL) {
        float m = act ? fmaxf(o.x, o.y) : -INFINITY;
#pragma unroll
        for (int off = 16; off; off >>= 1) m = fmaxf(m, __shfl_xor_sync(0xFFFFFFFFu, m, off));
        float s = act ? (expf(o.x - m) + expf(o.y - m)) : 0.f;
#pragma unroll
        for (int off = 16; off; off >>= 1) s += __shfl_xor_sync(0xFFFFFFFFu, s, off);
        float lse = m + logf(s);
        o.x -= lse;
        o.y -= lse;
    }
    if (act)
        *reinterpret_cast<float2*>(out + (size_t)w * DOUT + 2 * lane) = o;
}

// ---------------------------------------------------------------------------
extern "C" void kernel_launch(void* const* d_in, const int* in_sizes, int n_in,
                              void* d_out, int out_size) {
    const float* x   = (const float*)d_in[0];
    const int*   ei  = (const int*)d_in[1];
    const int*   src = ei;
    const int*   dst = ei + Ed;
    const float* Wl0 = (const float*)d_in[2];
    const float* bl0 = (const float*)d_in[3];
    const float* Wr0 = (const float*)d_in[4];
    const float* Wl1 = (const float*)d_in[5];
    const float* bl1 = (const float*)d_in[6];
    const float* Wr1 = (const float*)d_in[7];
    const float* Wl2 = (const float*)d_in[8];
    const float* bl2 = (const float*)d_in[9];
    const float* Wr2 = (const float*)d_in[10];
    float* out = (float*)d_out;

    __half* yp;
    float *pp, *h0p, *h1p;
    cudaGetSymbolAddress((void**)&yp,  g_y);
    cudaGetSymbolAddress((void**)&pp,  g_p);
    cudaGetSymbolAddress((void**)&h0p, g_h0);
    cudaGetSymbolAddress((void**)&h1p, g_h1);

    const int ngrid = (Nn + 255) / 256;
    const int egrid = (Ed + 255) / 256;
    const int ggrid = (Nn * 32 + 255) / 256;    // warp per node
    dim3 tblk(32, 8);
    const int tgrid = 888;

    // ---- CSR build (once per call, reused for all 3 layers) ----
    zero_deg_kernel<<<ngrid, 256>>>();
    deg_kernel<<<egrid, 256>>>(dst);
    scanA_kernel<<<NB_SCAN, 1024>>>();
    scanB_kernel<<<1, 128>>>();
    scanC_kernel<<<ngrid, 256>>>();
    fill_kernel<<<egrid, 256>>>(src, dst);

    // ---- Layer 0: x -> h0 ----
    transform_kernel<64><<<tgrid, tblk>>>(x, Wl0, bl0, Wr0, yp, pp);
    gather_kernel<64, true, false><<<ggrid, 256>>>(yp, pp, h0p);

    // ---- Layer 1: h0 -> h1 ----
    transform_kernel<64><<<tgrid, tblk>>>(h0p, Wl1, bl1, Wr1, yp, pp);
    gather_kernel<64, true, false><<<ggrid, 256>>>(yp, pp, h1p);

    // ---- Layer 2: h1 -> out (gather fused with log_softmax) ----
    transform_kernel<40><<<tgrid, tblk>>>(h1p, Wl2, bl2, Wr2, yp, pp);
    gather_kernel<40, false, true><<<ggrid, 256>>>(yp, pp, out);
}

// round 5
// speedup vs baseline: 3.9499x; 2.1108x over previous
#include <cuda_runtime.h>
#include <cuda_fp16.h>
#include <math.h>
#include <stdint.h>

constexpr int Nn = 100000;
constexpr int Ed = 1600000;
constexpr int DIN = 64;
constexpr int NB_SCAN = (Nn + 1023) / 1024;   // 98

// ---- scratch (device globals; no allocation allowed) ----------------------
__device__ __half g_y[(size_t)Nn * 64];       // h @ Wl   (fp16)
__device__ float  g_p[(size_t)Nn * 64];       // h @ Wr + bl (fp32)
__device__ float  g_h0[(size_t)Nn * 64];
__device__ float  g_h1[(size_t)Nn * 64];
__device__ int    g_csr_src[Ed];
__device__ int    g_rowptr[Nn];
__device__ int    g_rowloc[Nn];
__device__ int    g_cursor[Nn];
__device__ int    g_deg[Nn];
__device__ float  g_invdeg[Nn];
__device__ int    g_bsum[NB_SCAN];
__device__ int    g_bsumx[128];

// ---------------------------------------------------------------------------
__global__ void zero_deg_kernel() {
    int i = blockIdx.x * blockDim.x + threadIdx.x;
    if (i < Nn) g_deg[i] = 0;
}

__global__ void deg_kernel(const int* __restrict__ dst) {
    int e = blockIdx.x * blockDim.x + threadIdx.x;
    if (e < Ed) atomicAdd(&g_deg[__ldg(dst + e)], 1);
}

// ---- two-level exclusive scan of degrees -> rowptr (+ invdeg fused) -------
__global__ void scanA_kernel() {
    __shared__ int sh[1024];
    int tid = threadIdx.x;
    int i = blockIdx.x * 1024 + tid;
    int v = (i < Nn) ? g_deg[i] : 0;
    if (i < Nn) g_invdeg[i] = 1.0f / fmaxf((float)v, 1.0f);
    sh[tid] = v;
    __syncthreads();
#pragma unroll
    for (int off = 1; off < 1024; off <<= 1) {
        int t = (tid >= off) ? sh[tid - off] : 0;
        __syncthreads();
        sh[tid] += t;
        __syncthreads();
    }
    if (i < Nn) g_rowloc[i] = sh[tid] - v;
    if (tid == 1023) g_bsum[blockIdx.x] = sh[1023];
}

__global__ void scanB_kernel() {
    __shared__ int sh[128];
    int tid = threadIdx.x;
    int v = (tid < NB_SCAN) ? g_bsum[tid] : 0;
    sh[tid] = v;
    __syncthreads();
#pragma unroll
    for (int off = 1; off < 128; off <<= 1) {
        int t = (tid >= off) ? sh[tid - off] : 0;
        __syncthreads();
        sh[tid] += t;
        __syncthreads();
    }
    g_bsumx[tid] = sh[tid] - v;
}

__global__ void scanC_kernel() {
    int i = blockIdx.x * blockDim.x + threadIdx.x;
    if (i < Nn) {
        int r = g_rowloc[i] + g_bsumx[i >> 10];
        g_rowptr[i] = r;
        g_cursor[i] = r;
    }
}

__global__ void fill_kernel(const int* __restrict__ src,
                            const int* __restrict__ dst) {
    int e = blockIdx.x * blockDim.x + threadIdx.x;
    if (e < Ed) {
        int pos = atomicAdd(&g_cursor[__ldg(dst + e)], 1);
        g_csr_src[pos] = __ldg(src + e);
    }
}

// ---------------------------------------------------------------------------
// tf32 helpers
// ---------------------------------------------------------------------------
__device__ __forceinline__ uint32_t f2tf32(float x) {
    uint32_t r;
    asm("cvt.rna.tf32.f32 %0, %1;" : "=r"(r) : "f"(x));
    return r;
}

__device__ __forceinline__ void mma_tf32(float c[4], const uint32_t a[4],
                                         const uint32_t b0, const uint32_t b1) {
    asm volatile(
        "mma.sync.aligned.m16n8k8.row.col.f32.tf32.tf32.f32 "
        "{%0,%1,%2,%3}, {%4,%5,%6,%7}, {%8,%9}, {%0,%1,%2,%3};"
        : "+f"(c[0]), "+f"(c[1]), "+f"(c[2]), "+f"(c[3])
        : "r"(a[0]), "r"(a[1]), "r"(a[2]), "r"(a[3]), "r"(b0), "r"(b1));
}

// ---------------------------------------------------------------------------
// Transform via tf32 tensor cores.
// C[128 nodes x (2*DOUT)] = H[128 x 64] @ [Wl | Wr], bias on the right half.
// Left half -> y (fp16), right half -> p (fp32, +bl).
// Block = 256 threads (8 warps); warp w owns node rows [16w, 16w+16).
// Grid-strides over node tiles; W staged once per block.
// ---------------------------------------------------------------------------
template <int DOUT>
__global__ void transform_mma(const float* __restrict__ hin,
                              const float* __restrict__ Wl,
                              const float* __restrict__ bl,
                              const float* __restrict__ Wr,
                              __half* __restrict__ y,
                              float* __restrict__ p) {
    constexpr int NC  = 2 * DOUT;       // concat width (128 or 80)
    constexpr int NT  = NC / 8;         // n-tiles (16 or 10)
    constexpr int SWP = NC + 8;         // padded W stride (conflict-free)
    constexpr int SHP = 68;             // padded H stride (conflict-free)

    extern __shared__ uint32_t smem[];
    uint32_t* sW  = smem;                       // [64][SWP]
    uint32_t* sH  = smem + 64 * SWP;            // [128][SHP]
    float*    sbl = (float*)(smem + 64 * SWP + 128 * SHP);  // [DOUT]

    const int tid = threadIdx.x;
    const int w   = tid >> 5;
    const int l   = tid & 31;
    const int g   = l >> 2;       // group id (row within fragment)
    const int tig = l & 3;        // thread in group (col within fragment)

    // Stage weights (tf32) + bias, once per block
    for (int i = tid; i < 64 * DOUT; i += 256) {
        int k = i / DOUT, c = i - k * DOUT;
        sW[k * SWP + c]        = f2tf32(__ldg(Wl + i));
        sW[k * SWP + DOUT + c] = f2tf32(__ldg(Wr + i));
    }
    if (tid < DOUT) sbl[tid] = bl[tid];

    const int ntiles = (Nn + 127) / 128;
    for (int tile = blockIdx.x; tile < ntiles; tile += gridDim.x) {
        const int base = tile * 128;
        __syncthreads();
        // Stage H tile (tf32, padded): 128 rows x 64 cols
        for (int v = tid; v < 128 * 16; v += 256) {
            int r  = v >> 4;
            int c4 = (v & 15) * 4;
            int node = base + r;
            uint4 out4;
            if (node < Nn) {
                float4 hv = *reinterpret_cast<const float4*>(hin + (size_t)node * 64 + c4);
                out4.x = f2tf32(hv.x); out4.y = f2tf32(hv.y);
                out4.z = f2tf32(hv.z); out4.w = f2tf32(hv.w);
            } else {
                out4 = make_uint4(0, 0, 0, 0);
            }
            *reinterpret_cast<uint4*>(sH + r * SHP + c4) = out4;
        }
        __syncthreads();

        float c[NT][4];
#pragma unroll
        for (int nt = 0; nt < NT; nt++) {
            c[nt][0] = 0.f; c[nt][1] = 0.f; c[nt][2] = 0.f; c[nt][3] = 0.f;
        }

        const uint32_t* sHr0 = sH + (16 * w + g) * SHP;
        const uint32_t* sHr1 = sHr0 + 8 * SHP;
        const uint32_t* sWb  = sW + tig * SWP + g;

#pragma unroll
        for (int ks = 0; ks < 8; ks++) {
            const int k0 = ks * 8;
            uint32_t a[4];
            a[0] = sHr0[k0 + tig];
            a[1] = sHr1[k0 + tig];
            a[2] = sHr0[k0 + tig + 4];
            a[3] = sHr1[k0 + tig + 4];
#pragma unroll
            for (int nt = 0; nt < NT; nt++) {
                uint32_t b0 = sWb[k0 * SWP + nt * 8];
                uint32_t b1 = sWb[(k0 + 4) * SWP + nt * 8];
                mma_tf32(c[nt], a, b0, b1);
            }
        }

        // Epilogue
        const int node0 = base + 16 * w + g;
        const int node1 = node0 + 8;
#pragma unroll
        for (int nt = 0; nt < NT; nt++) {
            int col = nt * 8 + 2 * tig;
            if (col < DOUT) {
                if (node0 < Nn)
                    *reinterpret_cast<__half2*>(y + (size_t)node0 * DOUT + col) =
                        __floats2half2_rn(c[nt][0], c[nt][1]);
                if (node1 < Nn)
                    *reinterpret_cast<__half2*>(y + (size_t)node1 * DOUT + col) =
                        __floats2half2_rn(c[nt][2], c[nt][3]);
            } else {
                int pc = col - DOUT;
                float b0 = sbl[pc], b1 = sbl[pc + 1];
                if (node0 < Nn)
                    *reinterpret_cast<float2*>(p + (size_t)node0 * DOUT + pc) =
                        make_float2(c[nt][0] + b0, c[nt][1] + b1);
                if (node1 < Nn)
                    *reinterpret_cast<float2*>(p + (size_t)node1 * DOUT + pc) =
                        make_float2(c[nt][2] + b0, c[nt][3] + b1);
            }
        }
    }
}

// ---------------------------------------------------------------------------
// Gather: out[n] = act( invdeg[n] * sum_{j in N(n)} y[j] + p[n] )
// Warp per node; lane covers one half2; unrolled x8 (MLP).
// ---------------------------------------------------------------------------
template <int DOUT, bool RELU, bool FINAL>
__global__ void gather_kernel(const __half* __restrict__ y,
                              const float* __restrict__ p,
                              float* __restrict__ out) {
    int w = (blockIdx.x * blockDim.x + threadIdx.x) >> 5;
    int lane = threadIdx.x & 31;
    if (w >= Nn) return;
    const bool act = (2 * lane) < DOUT;

    const int start = g_rowptr[w];
    const int cnt   = g_deg[w];
    const int* __restrict__ idxp = g_csr_src + start;
    const __half2* __restrict__ y2 = reinterpret_cast<const __half2*>(y);
    constexpr int STRIDE = DOUT / 2;

    float2 acc = make_float2(0.f, 0.f);
    int i = 0;
    for (; i + 8 <= cnt; i += 8) {
        int s0 = __ldg(idxp + i + 0);
        int s1 = __ldg(idxp + i + 1);
        int s2 = __ldg(idxp + i + 2);
        int s3 = __ldg(idxp + i + 3);
        int s4 = __ldg(idxp + i + 4);
        int s5 = __ldg(idxp + i + 5);
        int s6 = __ldg(idxp + i + 6);
        int s7 = __ldg(idxp + i + 7);
        if (act) {
            __half2 v0 = __ldg(y2 + (size_t)s0 * STRIDE + lane);
            __half2 v1 = __ldg(y2 + (size_t)s1 * STRIDE + lane);
            __half2 v2 = __ldg(y2 + (size_t)s2 * STRIDE + lane);
            __half2 v3 = __ldg(y2 + (size_t)s3 * STRIDE + lane);
            __half2 v4 = __ldg(y2 + (size_t)s4 * STRIDE + lane);
            __half2 v5 = __ldg(y2 + (size_t)s5 * STRIDE + lane);
            __half2 v6 = __ldg(y2 + (size_t)s6 * STRIDE + lane);
            __half2 v7 = __ldg(y2 + (size_t)s7 * STRIDE + lane);
            float2 f0 = __half22float2(v0), f1 = __half22float2(v1);
            float2 f2 = __half22float2(v2), f3 = __half22float2(v3);
            float2 f4 = __half22float2(v4), f5 = __half22float2(v5);
            float2 f6 = __half22float2(v6), f7 = __half22float2(v7);
            acc.x += ((f0.x + f1.x) + (f2.x + f3.x)) + ((f4.x + f5.x) + (f6.x + f7.x));
            acc.y += ((f0.y + f1.y) + (f2.y + f3.y)) + ((f4.y + f5.y) + (f6.y + f7.y));
        }
    }
    for (; i < cnt; i++) {
        int s = __ldg(idxp + i);
        if (act) {
            float2 f = __half22float2(__ldg(y2 + (size_t)s * STRIDE + lane));
            acc.x += f.x;
            acc.y += f.y;
        }
    }

    float invd = g_invdeg[w];
    float2 o = make_float2(0.f, 0.f);
    if (act) {
        float2 pp = *reinterpret_cast<const float2*>(p + (size_t)w * DOUT + 2 * lane);
        o.x = fmaf(acc.x, invd, pp.x);
        o.y = fmaf(acc.y, invd, pp.y);
        if (RELU) { o.x = fmaxf(o.x, 0.f); o.y = fmaxf(o.y, 0.f); }
    }

    if (FINAL) {
        float m = act ? fmaxf(o.x, o.y) : -INFINITY;
#pragma unroll
        for (int off = 16; off; off >>= 1) m = fmaxf(m, __shfl_xor_sync(0xFFFFFFFFu, m, off));
        float s = act ? (expf(o.x - m) + expf(o.y - m)) : 0.f;
#pragma unroll
        for (int off = 16; off; off >>= 1) s += __shfl_xor_sync(0xFFFFFFFFu, s, off);
        float lse = m + logf(s);
        o.x -= lse;
        o.y -= lse;
    }
    if (act)
        *reinterpret_cast<float2*>(out + (size_t)w * DOUT + 2 * lane) = o;
}

// ---------------------------------------------------------------------------
extern "C" void kernel_launch(void* const* d_in, const int* in_sizes, int n_in,
                              void* d_out, int out_size) {
    const float* x   = (const float*)d_in[0];
    const int*   ei  = (const int*)d_in[1];
    const int*   src = ei;
    const int*   dst = ei + Ed;
    const float* Wl0 = (const float*)d_in[2];
    const float* bl0 = (const float*)d_in[3];
    const float* Wr0 = (const float*)d_in[4];
    const float* Wl1 = (const float*)d_in[5];
    const float* bl1 = (const float*)d_in[6];
    const float* Wr1 = (const float*)d_in[7];
    const float* Wl2 = (const float*)d_in[8];
    const float* bl2 = (const float*)d_in[9];
    const float* Wr2 = (const float*)d_in[10];
    float* out = (float*)d_out;

    __half* yp;
    float *pp, *h0p, *h1p;
    cudaGetSymbolAddress((void**)&yp,  g_y);
    cudaGetSymbolAddress((void**)&pp,  g_p);
    cudaGetSymbolAddress((void**)&h0p, g_h0);
    cudaGetSymbolAddress((void**)&h1p, g_h1);

    const int ngrid = (Nn + 255) / 256;
    const int egrid = (Ed + 255) / 256;
    const int ggrid = (Nn * 32 + 255) / 256;

    // Dynamic smem sizes for the two transform instantiations
    const int smem64 = (64 * (128 + 8) + 128 * 68 + 64) * 4;   // 69,888 B
    const int smem40 = (64 * (80 + 8)  + 128 * 68 + 40) * 4;   // 57,504 B
    static bool attr_set = false;
    cudaFuncSetAttribute(transform_mma<64>,
                         cudaFuncAttributeMaxDynamicSharedMemorySize, smem64);
    cudaFuncSetAttribute(transform_mma<40>,
                         cudaFuncAttributeMaxDynamicSharedMemorySize, smem40);
    (void)attr_set;

    const int tgrid = 444;   // ~3 blocks/SM, grid-stride over 782 tiles

    // ---- CSR build + layer 0 transform (reordered so launch #4 = transform
    //      for ncu visibility; T0 has no CSR dependency) ----
    zero_deg_kernel<<<ngrid, 256>>>();                                   // 1
    deg_kernel<<<egrid, 256>>>(dst);                                     // 2
    scanA_kernel<<<NB_SCAN, 1024>>>();                                   // 3
    transform_mma<64><<<tgrid, 256, smem64>>>(x, Wl0, bl0, Wr0, yp, pp); // 4
    scanB_kernel<<<1, 128>>>();                                          // 5
    scanC_kernel<<<ngrid, 256>>>();                                      // 6
    fill_kernel<<<egrid, 256>>>(src, dst);                               // 7

    // ---- Layer 0 gather ----
    gather_kernel<64, true, false><<<ggrid, 256>>>(yp, pp, h0p);         // 8

    // ---- Layer 1 ----
    transform_mma<64><<<tgrid, 256, smem64>>>(h0p, Wl1, bl1, Wr1, yp, pp); // 9
    gather_kernel<64, true, false><<<ggrid, 256>>>(yp, pp, h1p);           // 10

    // ---- Layer 2 (gather fused with log_softmax) ----
    transform_mma<40><<<tgrid, 256, smem40>>>(h1p, Wl2, bl2, Wr2, yp, pp); // 11
    gather_kernel<40, false, true><<<ggrid, 256>>>(yp, pp, out);           // 12
}

// round 6
// speedup vs baseline: 4.4443x; 1.1252x over previous
#include <cuda_runtime.h>
#include <cuda_fp16.h>
#include <math.h>
#include <stdint.h>

constexpr int Nn = 100000;
constexpr int Ed = 1600000;
constexpr int DIN = 64;
constexpr int NB_SCAN = (Nn + 1023) / 1024;   // 98

// ---- scratch (device globals; no allocation allowed) ----------------------
__device__ __half g_y[(size_t)Nn * 64];       // h @ Wl   (fp16)
__device__ float  g_p[(size_t)Nn * 64];       // h @ Wr + bl (fp32)
__device__ float  g_h0[(size_t)Nn * 64];
__device__ float  g_h1[(size_t)Nn * 64];
__device__ int    g_csr_src[Ed];
__device__ int    g_rowptr[Nn];
__device__ int    g_rowloc[Nn];
__device__ int    g_cursor[Nn];
__device__ int    g_deg[Nn];
__device__ float  g_invdeg[Nn];
__device__ int    g_bsum[NB_SCAN];
__device__ int    g_bsumx[128];

// ---------------------------------------------------------------------------
__global__ void zero_deg_kernel() {
    int i = blockIdx.x * blockDim.x + threadIdx.x;
    if (i < Nn) g_deg[i] = 0;
}

__global__ void deg_kernel(const int* __restrict__ dst) {
    int e = blockIdx.x * blockDim.x + threadIdx.x;
    if (e < Ed) atomicAdd(&g_deg[__ldg(dst + e)], 1);
}

// ---- two-level exclusive scan of degrees -> rowptr (+ invdeg fused) -------
__global__ void scanA_kernel() {
    __shared__ int sh[1024];
    int tid = threadIdx.x;
    int i = blockIdx.x * 1024 + tid;
    int v = (i < Nn) ? g_deg[i] : 0;
    if (i < Nn) g_invdeg[i] = 1.0f / fmaxf((float)v, 1.0f);
    sh[tid] = v;
    __syncthreads();
#pragma unroll
    for (int off = 1; off < 1024; off <<= 1) {
        int t = (tid >= off) ? sh[tid - off] : 0;
        __syncthreads();
        sh[tid] += t;
        __syncthreads();
    }
    if (i < Nn) g_rowloc[i] = sh[tid] - v;
    if (tid == 1023) g_bsum[blockIdx.x] = sh[1023];
}

__global__ void scanB_kernel() {
    __shared__ int sh[128];
    int tid = threadIdx.x;
    int v = (tid < NB_SCAN) ? g_bsum[tid] : 0;
    sh[tid] = v;
    __syncthreads();
#pragma unroll
    for (int off = 1; off < 128; off <<= 1) {
        int t = (tid >= off) ? sh[tid - off] : 0;
        __syncthreads();
        sh[tid] += t;
        __syncthreads();
    }
    g_bsumx[tid] = sh[tid] - v;
}

__global__ void scanC_kernel() {
    int i = blockIdx.x * blockDim.x + threadIdx.x;
    if (i < Nn) {
        int r = g_rowloc[i] + g_bsumx[i >> 10];
        g_rowptr[i] = r;
        g_cursor[i] = r;
    }
}

__global__ void fill_kernel(const int* __restrict__ src,
                            const int* __restrict__ dst) {
    int e = blockIdx.x * blockDim.x + threadIdx.x;
    if (e < Ed) {
        int pos = atomicAdd(&g_cursor[__ldg(dst + e)], 1);
        g_csr_src[pos] = __ldg(src + e);
    }
}

// ---------------------------------------------------------------------------
// tf32 helpers
// ---------------------------------------------------------------------------
__device__ __forceinline__ uint32_t f2tf32(float x) {
    uint32_t r;
    asm("cvt.rna.tf32.f32 %0, %1;" : "=r"(r) : "f"(x));
    return r;
}

__device__ __forceinline__ void mma_tf32(float c[4], const uint32_t a[4],
                                         const uint32_t b0, const uint32_t b1) {
    asm volatile(
        "mma.sync.aligned.m16n8k8.row.col.f32.tf32.tf32.f32 "
        "{%0,%1,%2,%3}, {%4,%5,%6,%7}, {%8,%9}, {%0,%1,%2,%3};"
        : "+f"(c[0]), "+f"(c[1]), "+f"(c[2]), "+f"(c[3])
        : "r"(a[0]), "r"(a[1]), "r"(a[2]), "r"(a[3]), "r"(b0), "r"(b1));
}

// ---------------------------------------------------------------------------
// Transform via tf32 tensor cores.
// C[128 nodes x (2*DOUT)] = H[128 x 64] @ [Wl | Wr]; left->y(fp16), right->p(+bl).
// W staged in MMA-FRAGMENT ORDER: uint4 per lane per (ks, nt-pair) so the
// inner loop does a single conflict-free LDS.128 per two n-tiles.
// ---------------------------------------------------------------------------
template <int DOUT>
__global__ void transform_mma(const float* __restrict__ hin,
                              const float* __restrict__ Wl,
                              const float* __restrict__ bl,
                              const float* __restrict__ Wr,
                              __half* __restrict__ y,
                              float* __restrict__ p) {
    constexpr int NC  = 2 * DOUT;       // concat width (128 or 80)
    constexpr int NT  = NC / 8;         // n-tiles (16 or 10)
    constexpr int NQ  = NT / 2;         // n-tile pairs (8 or 5)
    constexpr int SHP = 68;             // padded H stride (conflict-free)
    constexpr int WF_WORDS = 8 * NQ * 32 * 4;   // fragment-ordered W

    extern __shared__ uint32_t smem[];
    uint32_t* sWf = smem;                               // [8][NQ][32] x uint4
    uint32_t* sH  = smem + WF_WORDS;                    // [128][SHP]
    float*    sbl = (float*)(smem + WF_WORDS + 128 * SHP);

    const int tid = threadIdx.x;
    const int w   = tid >> 5;
    const int l   = tid & 31;
    const int g   = l >> 2;       // fragment row group
    const int tig = l & 3;        // thread in group

    // Stage W in fragment order: entry (ks, q, lane) holds
    // {b0(nt=2q), b1(2q), b0(2q+1), b1(2q+1)} for that lane.
    // b0(nt) = W[ks*8+tig][8*nt+g], b1(nt) = W[ks*8+tig+4][8*nt+g],
    // where W = [Wl | Wr] concatenated along columns.
    for (int idx = tid; idx < 8 * NQ * 32; idx += 256) {
        int ks  = idx / (NQ * 32);
        int rem = idx - ks * (NQ * 32);
        int q   = rem >> 5;
        int ll  = rem & 31;
        int gg  = ll >> 2;
        int tt  = ll & 3;
        int k_lo = ks * 8 + tt;
        int k_hi = k_lo + 4;
        uint4 frag;
        {
            int cc = (2 * q) * 8 + gg;
            const float* basev = (cc < DOUT) ? (Wl + cc) : (Wr + cc - DOUT);
            frag.x = f2tf32(__ldg(basev + k_lo * DOUT));
            frag.y = f2tf32(__ldg(basev + k_hi * DOUT));
        }
        {
            int cc = (2 * q + 1) * 8 + gg;
            const float* basev = (cc < DOUT) ? (Wl + cc) : (Wr + cc - DOUT);
            frag.z = f2tf32(__ldg(basev + k_lo * DOUT));
            frag.w = f2tf32(__ldg(basev + k_hi * DOUT));
        }
        reinterpret_cast<uint4*>(sWf)[idx] = frag;
    }
    if (tid < DOUT) sbl[tid] = bl[tid];

    const uint4* wf = reinterpret_cast<const uint4*>(sWf) + l;

    const int ntiles = (Nn + 127) / 128;
    for (int tile = blockIdx.x; tile < ntiles; tile += gridDim.x) {
        const int base = tile * 128;
        __syncthreads();
        // Stage H tile (tf32, padded): 128 rows x 64 cols
        for (int v = tid; v < 128 * 16; v += 256) {
            int r  = v >> 4;
            int c4 = (v & 15) * 4;
            int node = base + r;
            uint4 out4;
            if (node < Nn) {
                float4 hv = *reinterpret_cast<const float4*>(hin + (size_t)node * 64 + c4);
                out4.x = f2tf32(hv.x); out4.y = f2tf32(hv.y);
                out4.z = f2tf32(hv.z); out4.w = f2tf32(hv.w);
            } else {
                out4 = make_uint4(0, 0, 0, 0);
            }
            *reinterpret_cast<uint4*>(sH + r * SHP + c4) = out4;
        }
        __syncthreads();

        float c[NT][4];
#pragma unroll
        for (int nt = 0; nt < NT; nt++) {
            c[nt][0] = 0.f; c[nt][1] = 0.f; c[nt][2] = 0.f; c[nt][3] = 0.f;
        }

        const uint32_t* sHr0 = sH + (16 * w + g) * SHP;
        const uint32_t* sHr1 = sHr0 + 8 * SHP;

#pragma unroll
        for (int ks = 0; ks < 8; ks++) {
            const int k0 = ks * 8;
            uint32_t a[4];
            a[0] = sHr0[k0 + tig];
            a[1] = sHr1[k0 + tig];
            a[2] = sHr0[k0 + tig + 4];
            a[3] = sHr1[k0 + tig + 4];
#pragma unroll
            for (int q = 0; q < NQ; q++) {
                uint4 b = wf[(ks * NQ + q) * 32];
                mma_tf32(c[2 * q],     a, b.x, b.y);
                mma_tf32(c[2 * q + 1], a, b.z, b.w);
            }
        }

        // Epilogue
        const int node0 = base + 16 * w + g;
        const int node1 = node0 + 8;
#pragma unroll
        for (int nt = 0; nt < NT; nt++) {
            int col = nt * 8 + 2 * tig;
            if (col < DOUT) {
                if (node0 < Nn)
                    *reinterpret_cast<__half2*>(y + (size_t)node0 * DOUT + col) =
                        __floats2half2_rn(c[nt][0], c[nt][1]);
                if (node1 < Nn)
                    *reinterpret_cast<__half2*>(y + (size_t)node1 * DOUT + col) =
                        __floats2half2_rn(c[nt][2], c[nt][3]);
            } else {
                int pc = col - DOUT;
                float b0 = sbl[pc], b1 = sbl[pc + 1];
                if (node0 < Nn)
                    *reinterpret_cast<float2*>(p + (size_t)node0 * DOUT + pc) =
                        make_float2(c[nt][0] + b0, c[nt][1] + b1);
                if (node1 < Nn)
                    *reinterpret_cast<float2*>(p + (size_t)node1 * DOUT + pc) =
                        make_float2(c[nt][2] + b0, c[nt][3] + b1);
            }
        }
    }
}

// ---------------------------------------------------------------------------
// Gather: out[n] = act( invdeg[n] * sum_{j in N(n)} y[j] + p[n] )
// ---------------------------------------------------------------------------
template <int DOUT, bool RELU, bool FINAL>
__global__ void gather_kernel(const __half* __restrict__ y,
                              const float* __restrict__ p,
                              float* __restrict__ out) {
    int w = (blockIdx.x * blockDim.x + threadIdx.x) >> 5;
    int lane = threadIdx.x & 31;
    if (w >= Nn) return;
    const bool act = (2 * lane) < DOUT;

    const int start = g_rowptr[w];
    const int cnt   = g_deg[w];
    const int* __restrict__ idxp = g_csr_src + start;
    const __half2* __restrict__ y2 = reinterpret_cast<const __half2*>(y);
    constexpr int STRIDE = DOUT / 2;

    float2 acc = make_float2(0.f, 0.f);
    int i = 0;
    for (; i + 8 <= cnt; i += 8) {
        int s0 = __ldg(idxp + i + 0);
        int s1 = __ldg(idxp + i + 1);
        int s2 = __ldg(idxp + i + 2);
        int s3 = __ldg(idxp + i + 3);
        int s4 = __ldg(idxp + i + 4);
        int s5 = __ldg(idxp + i + 5);
        int s6 = __ldg(idxp + i + 6);
        int s7 = __ldg(idxp + i + 7);
        if (act) {
            __half2 v0 = __ldg(y2 + (size_t)s0 * STRIDE + lane);
            __half2 v1 = __ldg(y2 + (size_t)s1 * STRIDE + lane);
            __half2 v2 = __ldg(y2 + (size_t)s2 * STRIDE + lane);
            __half2 v3 = __ldg(y2 + (size_t)s3 * STRIDE + lane);
            __half2 v4 = __ldg(y2 + (size_t)s4 * STRIDE + lane);
            __half2 v5 = __ldg(y2 + (size_t)s5 * STRIDE + lane);
            __half2 v6 = __ldg(y2 + (size_t)s6 * STRIDE + lane);
            __half2 v7 = __ldg(y2 + (size_t)s7 * STRIDE + lane);
            float2 f0 = __half22float2(v0), f1 = __half22float2(v1);
            float2 f2 = __half22float2(v2), f3 = __half22float2(v3);
            float2 f4 = __half22float2(v4), f5 = __half22float2(v5);
            float2 f6 = __half22float2(v6), f7 = __half22float2(v7);
            acc.x += ((f0.x + f1.x) + (f2.x + f3.x)) + ((f4.x + f5.x) + (f6.x + f7.x));
            acc.y += ((f0.y + f1.y) + (f2.y + f3.y)) + ((f4.y + f5.y) + (f6.y + f7.y));
        }
    }
    for (; i < cnt; i++) {
        int s = __ldg(idxp + i);
        if (act) {
            float2 f = __half22float2(__ldg(y2 + (size_t)s * STRIDE + lane));
            acc.x += f.x;
            acc.y += f.y;
        }
    }

    float invd = g_invdeg[w];
    float2 o = make_float2(0.f, 0.f);
    if (act) {
        float2 pp = *reinterpret_cast<const float2*>(p + (size_t)w * DOUT + 2 * lane);
        o.x = fmaf(acc.x, invd, pp.x);
        o.y = fmaf(acc.y, invd, pp.y);
        if (RELU) { o.x = fmaxf(o.x, 0.f); o.y = fmaxf(o.y, 0.f); }
    }

    if (FINAL) {
        float m = act ? fmaxf(o.x, o.y) : -INFINITY;
#pragma unroll
        for (int off = 16; off; off >>= 1) m = fmaxf(m, __shfl_xor_sync(0xFFFFFFFFu, m, off));
        float s = act ? (expf(o.x - m) + expf(o.y - m)) : 0.f;
#pragma unroll
        for (int off = 16; off; off >>= 1) s += __shfl_xor_sync(0xFFFFFFFFu, s, off);
        float lse = m + logf(s);
        o.x -= lse;
        o.y -= lse;
    }
    if (act)
        *reinterpret_cast<float2*>(out + (size_t)w * DOUT + 2 * lane) = o;
}

// ---------------------------------------------------------------------------
extern "C" void kernel_launch(void* const* d_in, const int* in_sizes, int n_in,
                              void* d_out, int out_size) {
    const float* x   = (const float*)d_in[0];
    const int*   ei  = (const int*)d_in[1];
    const int*   src = ei;
    const int*   dst = ei + Ed;
    const float* Wl0 = (const float*)d_in[2];
    const float* bl0 = (const float*)d_in[3];
    const float* Wr0 = (const float*)d_in[4];
    const float* Wl1 = (const float*)d_in[5];
    const float* bl1 = (const float*)d_in[6];
    const float* Wr1 = (const float*)d_in[7];
    const float* Wl2 = (const float*)d_in[8];
    const float* bl2 = (const float*)d_in[9];
    const float* Wr2 = (const float*)d_in[10];
    float* out = (float*)d_out;

    __half* yp;
    float *pp, *h0p, *h1p;
    cudaGetSymbolAddress((void**)&yp,  g_y);
    cudaGetSymbolAddress((void**)&pp,  g_p);
    cudaGetSymbolAddress((void**)&h0p, g_h0);
    cudaGetSymbolAddress((void**)&h1p, g_h1);

    const int ngrid = (Nn + 255) / 256;
    const int egrid = (Ed + 255) / 256;
    const int ggrid = (Nn * 32 + 255) / 256;

    // Dynamic smem: fragment-ordered W + padded H + bias
    const int smem64 = (8 * 8 * 32 * 4 + 128 * 68 + 64) * 4;  // 67,840 B
    const int smem40 = (8 * 5 * 32 * 4 + 128 * 68 + 40) * 4;  // 55,616 B
    cudaFuncSetAttribute(transform_mma<64>,
                         cudaFuncAttributeMaxDynamicSharedMemorySize, smem64);
    cudaFuncSetAttribute(transform_mma<40>,
                         cudaFuncAttributeMaxDynamicSharedMemorySize, smem40);

    const int tgrid = 296;   // 2 resident blocks/SM, grid-stride over 782 tiles

    // Second stream + fork/join events, created once (first call is the
    // uncaptured correctness run; subsequent captured calls reuse them).
    static cudaStream_t s2 = nullptr;
    static cudaEvent_t evFork = nullptr, evJoin = nullptr;
    if (s2 == nullptr) {
        cudaStreamCreateWithFlags(&s2, cudaStreamNonBlocking);
        cudaEventCreateWithFlags(&evFork, cudaEventDisableTiming);
        cudaEventCreateWithFlags(&evJoin, cudaEventDisableTiming);
    }

    // ---- Fork: transform0 (only needs x, W) on s2, CSR build on stream 0 ----
    cudaEventRecord(evFork, 0);
    cudaStreamWaitEvent(s2, evFork, 0);
    transform_mma<64><<<tgrid, 256, smem64, s2>>>(x, Wl0, bl0, Wr0, yp, pp);
    cudaEventRecord(evJoin, s2);

    zero_deg_kernel<<<ngrid, 256>>>();
    deg_kernel<<<egrid, 256>>>(dst);
    scanA_kernel<<<NB_SCAN, 1024>>>();
    scanB_kernel<<<1, 128>>>();
    scanC_kernel<<<ngrid, 256>>>();
    fill_kernel<<<egrid, 256>>>(src, dst);

    // ---- Join, then layer 0 gather ----
    cudaStreamWaitEvent(0, evJoin, 0);
    gather_kernel<64, true, false><<<ggrid, 256>>>(yp, pp, h0p);

    // ---- Layer 1 ----
    transform_mma<64><<<tgrid, 256, smem64>>>(h0p, Wl1, bl1, Wr1, yp, pp);
    gather_kernel<64, true, false><<<ggrid, 256>>>(yp, pp, h1p);

    // ---- Layer 2 (gather fused with log_softmax) ----
    transform_mma<40><<<tgrid, 256, smem40>>>(h1p, Wl2, bl2, Wr2, yp, pp);
    gather_kernel<40, false, true><<<ggrid, 256>>>(yp, pp, out);
}

// round 7
// speedup vs baseline: 4.5272x; 1.0187x over previous
#include <cuda_runtime.h>
#include <cuda_fp16.h>
#include <math.h>
#include <stdint.h>

constexpr int Nn = 100000;
constexpr int Ed = 1600000;
constexpr int DIN = 64;
constexpr int NB_SCAN = (Nn + 1023) / 1024;   // 98

// ---- scratch (device globals; no allocation allowed) ----------------------
__device__ __half g_y[(size_t)Nn * 64];       // h @ Wl   (fp16)
__device__ float  g_p[(size_t)Nn * 64];       // h @ Wr + bl (fp32)
__device__ float  g_h0[(size_t)Nn * 64];
__device__ float  g_h1[(size_t)Nn * 64];
__device__ int    g_csr_src[Ed];
__device__ int    g_rowptr[Nn];
__device__ int    g_rowloc[Nn];
__device__ int    g_cursor[Nn];
__device__ int    g_deg[Nn];
__device__ float  g_invdeg[Nn];
__device__ int    g_bsum[NB_SCAN];

// ---------------------------------------------------------------------------
__global__ void zero_deg_kernel() {
    int i = blockIdx.x * blockDim.x + threadIdx.x;
    if (i < Nn) g_deg[i] = 0;
}

// 4 edges per thread (Ed % 4 == 0)
__global__ void deg_kernel(const int* __restrict__ dst) {
    int e4 = blockIdx.x * blockDim.x + threadIdx.x;
    if (e4 < Ed / 4) {
        int4 d = __ldg(reinterpret_cast<const int4*>(dst) + e4);
        atomicAdd(&g_deg[d.x], 1);
        atomicAdd(&g_deg[d.y], 1);
        atomicAdd(&g_deg[d.z], 1);
        atomicAdd(&g_deg[d.w], 1);
    }
}

// ---- scan of degrees -> rowptr (+ invdeg fused) ---------------------------
__global__ void scanA_kernel() {
    __shared__ int sh[1024];
    int tid = threadIdx.x;
    int i = blockIdx.x * 1024 + tid;
    int v = (i < Nn) ? g_deg[i] : 0;
    if (i < Nn) g_invdeg[i] = 1.0f / fmaxf((float)v, 1.0f);
    sh[tid] = v;
    __syncthreads();
#pragma unroll
    for (int off = 1; off < 1024; off <<= 1) {
        int t = (tid >= off) ? sh[tid - off] : 0;
        __syncthreads();
        sh[tid] += t;
        __syncthreads();
    }
    if (i < Nn) g_rowloc[i] = sh[tid] - v;
    if (tid == 1023) g_bsum[blockIdx.x] = sh[1023];
}

// scanC with the 98-partial reduction folded in (scanB eliminated)
__global__ void scanC_kernel() {
    __shared__ int sb[NB_SCAN];
    int tid = threadIdx.x;
    for (int j = tid; j < NB_SCAN; j += 256) sb[j] = g_bsum[j];
    __syncthreads();
    int i = blockIdx.x * 256 + tid;
    if (i < Nn) {
        int blk = i >> 10;
        int off = 0;
        for (int j = 0; j < blk; j++) off += sb[j];
        int r = g_rowloc[i] + off;
        g_rowptr[i] = r;
        g_cursor[i] = r;
    }
}

// 4 edges per thread
__global__ void fill_kernel(const int* __restrict__ src,
                            const int* __restrict__ dst) {
    int e4 = blockIdx.x * blockDim.x + threadIdx.x;
    if (e4 < Ed / 4) {
        int4 s = __ldg(reinterpret_cast<const int4*>(src) + e4);
        int4 d = __ldg(reinterpret_cast<const int4*>(dst) + e4);
        g_csr_src[atomicAdd(&g_cursor[d.x], 1)] = s.x;
        g_csr_src[atomicAdd(&g_cursor[d.y], 1)] = s.y;
        g_csr_src[atomicAdd(&g_cursor[d.z], 1)] = s.z;
        g_csr_src[atomicAdd(&g_cursor[d.w], 1)] = s.w;
    }
}

// ---------------------------------------------------------------------------
// helpers
// ---------------------------------------------------------------------------
__device__ __forceinline__ uint32_t f2tf32(float x) {
    uint32_t r;
    asm("cvt.rna.tf32.f32 %0, %1;" : "=r"(r) : "f"(x));
    return r;
}

__device__ __forceinline__ void mma_tf32(float c[4], const uint32_t a[4],
                                         const uint32_t b0, const uint32_t b1) {
    asm volatile(
        "mma.sync.aligned.m16n8k8.row.col.f32.tf32.tf32.f32 "
        "{%0,%1,%2,%3}, {%4,%5,%6,%7}, {%8,%9}, {%0,%1,%2,%3};"
        : "+f"(c[0]), "+f"(c[1]), "+f"(c[2]), "+f"(c[3])
        : "r"(a[0]), "r"(a[1]), "r"(a[2]), "r"(a[3]), "r"(b0), "r"(b1));
}

__device__ __forceinline__ uint32_t s2u(const void* p) {
    uint32_t a;
    asm("{.reg .u64 t; cvta.to.shared.u64 t, %1; cvt.u32.u64 %0, t;}"
        : "=r"(a) : "l"(p));
    return a;
}

__device__ __forceinline__ void cp16(uint32_t dst, const void* src) {
    asm volatile("cp.async.cg.shared.global [%0], [%1], 16;"
                 :: "r"(dst), "l"(src));
}

// ---------------------------------------------------------------------------
// Transform via tf32 tensor cores, cp.async double-buffered H staging.
// C[128 x 2*DOUT] = H[128 x 64] @ [Wl | Wr]; left->y(fp16), right->p(fp32,+bl).
// W pre-swizzled into mma-fragment order (one LDS.128 per two n-tiles).
// H staged as raw fp32 via cp.async; tf32 convert at A-fragment load.
// ---------------------------------------------------------------------------
template <int DOUT>
__global__ void transform_mma(const float* __restrict__ hin,
                              const float* __restrict__ Wl,
                              const float* __restrict__ bl,
                              const float* __restrict__ Wr,
                              __half* __restrict__ y,
                              float* __restrict__ p) {
    constexpr int NC  = 2 * DOUT;
    constexpr int NT  = NC / 8;
    constexpr int NQ  = NT / 2;
    constexpr int SHP = 68;                     // floats per padded H row
    constexpr int WF_WORDS = 8 * NQ * 32 * 4;

    extern __shared__ uint32_t smem[];
    uint32_t* sWf = smem;
    float* sHA = (float*)(smem + WF_WORDS);
    float* sHB = sHA + 128 * SHP;
    float* sbl = sHB + 128 * SHP;

    const int tid = threadIdx.x;
    const int w   = tid >> 5;
    const int l   = tid & 31;
    const int g   = l >> 2;
    const int tig = l & 3;

    // Stage W in fragment order (see R6); synced by the first pipeline sync.
    for (int idx = tid; idx < 8 * NQ * 32; idx += 256) {
        int ks  = idx / (NQ * 32);
        int rem = idx - ks * (NQ * 32);
        int q   = rem >> 5;
        int ll  = rem & 31;
        int gg  = ll >> 2;
        int tt  = ll & 3;
        int k_lo = ks * 8 + tt;
        int k_hi = k_lo + 4;
        uint4 frag;
        {
            int cc = (2 * q) * 8 + gg;
            const float* basev = (cc < DOUT) ? (Wl + cc) : (Wr + cc - DOUT);
            frag.x = f2tf32(__ldg(basev + k_lo * DOUT));
            frag.y = f2tf32(__ldg(basev + k_hi * DOUT));
        }
        {
            int cc = (2 * q + 1) * 8 + gg;
            const float* basev = (cc < DOUT) ? (Wl + cc) : (Wr + cc - DOUT);
            frag.z = f2tf32(__ldg(basev + k_lo * DOUT));
            frag.w = f2tf32(__ldg(basev + k_hi * DOUT));
        }
        reinterpret_cast<uint4*>(sWf)[idx] = frag;
    }
    if (tid < DOUT) sbl[tid] = bl[tid];

    const uint4* wf = reinterpret_cast<const uint4*>(sWf) + l;
    const int ntiles = (Nn + 127) / 128;

    // Stage one H tile into buf via cp.async; ALWAYS commits a group.
    auto stage = [&](int tile, float* buf) {
        if (tile < ntiles) {
            const int base = tile * 128;
            const uint32_t bufu = s2u(buf);
            for (int v = tid; v < 2048; v += 256) {      // 128 rows x 4 chunks
                int r  = v >> 4;
                int cb = (v & 15) * 16;                  // byte offset in row
                int node = base + r;
                uint32_t d = bufu + (uint32_t)(r * (SHP * 4) + cb);
                if (node < Nn)
                    cp16(d, (const char*)(hin + (size_t)node * 64) + cb);
                else
                    *reinterpret_cast<float4*>((char*)buf + r * (SHP * 4) + cb) =
                        make_float4(0.f, 0.f, 0.f, 0.f);
            }
        }
        asm volatile("cp.async.commit_group;");
    };

    float* cur = sHA;
    float* nxt = sHB;
    int tile = blockIdx.x;
    stage(tile, cur);

    for (; tile < ntiles; tile += gridDim.x) {
        stage(tile + gridDim.x, nxt);
        asm volatile("cp.async.wait_group 1;");
        __syncthreads();

        float c[NT][4];
#pragma unroll
        for (int nt = 0; nt < NT; nt++) {
            c[nt][0] = 0.f; c[nt][1] = 0.f; c[nt][2] = 0.f; c[nt][3] = 0.f;
        }

        const float* sHr0 = cur + (16 * w + g) * SHP;
        const float* sHr1 = sHr0 + 8 * SHP;

#pragma unroll
        for (int ks = 0; ks < 8; ks++) {
            const int k0 = ks * 8;
            uint32_t a[4];
            a[0] = f2tf32(sHr0[k0 + tig]);
            a[1] = f2tf32(sHr1[k0 + tig]);
            a[2] = f2tf32(sHr0[k0 + tig + 4]);
            a[3] = f2tf32(sHr1[k0 + tig + 4]);
#pragma unroll
            for (int q = 0; q < NQ; q++) {
                uint4 b = wf[(ks * NQ + q) * 32];
                mma_tf32(c[2 * q],     a, b.x, b.y);
                mma_tf32(c[2 * q + 1], a, b.z, b.w);
            }
        }

        const int base = tile * 128;
        const int node0 = base + 16 * w + g;
        const int node1 = node0 + 8;
#pragma unroll
        for (int nt = 0; nt < NT; nt++) {
            int col = nt * 8 + 2 * tig;
            if (col < DOUT) {
                if (node0 < Nn)
                    *reinterpret_cast<__half2*>(y + (size_t)node0 * DOUT + col) =
                        __floats2half2_rn(c[nt][0], c[nt][1]);
                if (node1 < Nn)
                    *reinterpret_cast<__half2*>(y + (size_t)node1 * DOUT + col) =
                        __floats2half2_rn(c[nt][2], c[nt][3]);
            } else {
                int pc = col - DOUT;
                float b0 = sbl[pc], b1 = sbl[pc + 1];
                if (node0 < Nn)
                    *reinterpret_cast<float2*>(p + (size_t)node0 * DOUT + pc) =
                        make_float2(c[nt][0] + b0, c[nt][1] + b1);
                if (node1 < Nn)
                    *reinterpret_cast<float2*>(p + (size_t)node1 * DOUT + pc) =
                        make_float2(c[nt][2] + b0, c[nt][3] + b1);
            }
        }
        __syncthreads();   // done reading cur before it is restaged
        float* t = cur; cur = nxt; nxt = t;
    }
}

// ---------------------------------------------------------------------------
// Gather: out[n] = act( invdeg[n] * sum_{j in N(n)} y[j] + p[n] )
// ---------------------------------------------------------------------------
template <int DOUT, bool RELU, bool FINAL>
__global__ void gather_kernel(const __half* __restrict__ y,
                              const float* __restrict__ p,
                              float* __restrict__ out) {
    int w = (blockIdx.x * blockDim.x + threadIdx.x) >> 5;
    int lane = threadIdx.x & 31;
    if (w >= Nn) return;
    const bool act = (2 * lane) < DOUT;

    const int start = g_rowptr[w];
    const int cnt   = g_deg[w];
    const int* __restrict__ idxp = g_csr_src + start;
    const __half2* __restrict__ y2 = reinterpret_cast<const __half2*>(y);
    constexpr int STRIDE = DOUT / 2;

    float2 acc = make_float2(0.f, 0.f);
    int i = 0;
    for (; i + 8 <= cnt; i += 8) {
        int s0 = __ldg(idxp + i + 0);
        int s1 = __ldg(idxp + i + 1);
        int s2 = __ldg(idxp + i + 2);
        int s3 = __ldg(idxp + i + 3);
        int s4 = __ldg(idxp + i + 4);
        int s5 = __ldg(idxp + i + 5);
        int s6 = __ldg(idxp + i + 6);
        int s7 = __ldg(idxp + i + 7);
        if (act) {
            __half2 v0 = __ldg(y2 + (size_t)s0 * STRIDE + lane);
            __half2 v1 = __ldg(y2 + (size_t)s1 * STRIDE + lane);
            __half2 v2 = __ldg(y2 + (size_t)s2 * STRIDE + lane);
            __half2 v3 = __ldg(y2 + (size_t)s3 * STRIDE + lane);
            __half2 v4 = __ldg(y2 + (size_t)s4 * STRIDE + lane);
            __half2 v5 = __ldg(y2 + (size_t)s5 * STRIDE + lane);
            __half2 v6 = __ldg(y2 + (size_t)s6 * STRIDE + lane);
            __half2 v7 = __ldg(y2 + (size_t)s7 * STRIDE + lane);
            float2 f0 = __half22float2(v0), f1 = __half22float2(v1);
            float2 f2 = __half22float2(v2), f3 = __half22float2(v3);
            float2 f4 = __half22float2(v4), f5 = __half22float2(v5);
            float2 f6 = __half22float2(v6), f7 = __half22float2(v7);
            acc.x += ((f0.x + f1.x) + (f2.x + f3.x)) + ((f4.x + f5.x) + (f6.x + f7.x));
            acc.y += ((f0.y + f1.y) + (f2.y + f3.y)) + ((f4.y + f5.y) + (f6.y + f7.y));
        }
    }
    for (; i < cnt; i++) {
        int s = __ldg(idxp + i);
        if (act) {
            float2 f = __half22float2(__ldg(y2 + (size_t)s * STRIDE + lane));
            acc.x += f.x;
            acc.y += f.y;
        }
    }

    float invd = g_invdeg[w];
    float2 o = make_float2(0.f, 0.f);
    if (act) {
        float2 pp = *reinterpret_cast<const float2*>(p + (size_t)w * DOUT + 2 * lane);
        o.x = fmaf(acc.x, invd, pp.x);
        o.y = fmaf(acc.y, invd, pp.y);
        if (RELU) { o.x = fmaxf(o.x, 0.f); o.y = fmaxf(o.y, 0.f); }
    }

    if (FINAL) {
        float m = act ? fmaxf(o.x, o.y) : -INFINITY;
#pragma unroll
        for (int off = 16; off; off >>= 1) m = fmaxf(m, __shfl_xor_sync(0xFFFFFFFFu, m, off));
        float s = act ? (expf(o.x - m) + expf(o.y - m)) : 0.f;
#pragma unroll
        for (int off = 16; off; off >>= 1) s += __shfl_xor_sync(0xFFFFFFFFu, s, off);
        float lse = m + logf(s);
        o.x -= lse;
        o.y -= lse;
    }
    if (act)
        *reinterpret_cast<float2*>(out + (size_t)w * DOUT + 2 * lane) = o;
}

// ---------------------------------------------------------------------------
extern "C" void kernel_launch(void* const* d_in, const int* in_sizes, int n_in,
                              void* d_out, int out_size) {
    const float* x   = (const float*)d_in[0];
    const int*   ei  = (const int*)d_in[1];
    const int*   src = ei;
    const int*   dst = ei + Ed;
    const float* Wl0 = (const float*)d_in[2];
    const float* bl0 = (const float*)d_in[3];
    const float* Wr0 = (const float*)d_in[4];
    const float* Wl1 = (const float*)d_in[5];
    const float* bl1 = (const float*)d_in[6];
    const float* Wr1 = (const float*)d_in[7];
    const float* Wl2 = (const float*)d_in[8];
    const float* bl2 = (const float*)d_in[9];
    const float* Wr2 = (const float*)d_in[10];
    float* out = (float*)d_out;

    __half* yp;
    float *pp, *h0p, *h1p;
    cudaGetSymbolAddress((void**)&yp,  g_y);
    cudaGetSymbolAddress((void**)&pp,  g_p);
    cudaGetSymbolAddress((void**)&h0p, g_h0);
    cudaGetSymbolAddress((void**)&h1p, g_h1);

    const int ngrid  = (Nn + 255) / 256;
    const int e4grid = (Ed / 4 + 255) / 256;
    const int ggrid  = (Nn * 32 + 255) / 256;

    // smem: fragment W + 2 fp32 H buffers + bias
    const int smem64 = (8 * 8 * 32 * 4) * 4 + 2 * 128 * 68 * 4 + 64 * 4;  // 102,656
    const int smem40 = (8 * 5 * 32 * 4) * 4 + 2 * 128 * 68 * 4 + 40 * 4;  //  90,272
    cudaFuncSetAttribute(transform_mma<64>,
                         cudaFuncAttributeMaxDynamicSharedMemorySize, smem64);
    cudaFuncSetAttribute(transform_mma<40>,
                         cudaFuncAttributeMaxDynamicSharedMemorySize, smem40);

    const int tgrid = 296;   // 2 resident blocks/SM

    static cudaStream_t s2 = nullptr;
    static cudaEvent_t evFork = nullptr, evJoin = nullptr;
    if (s2 == nullptr) {
        cudaStreamCreateWithFlags(&s2, cudaStreamNonBlocking);
        cudaEventCreateWithFlags(&evFork, cudaEventDisableTiming);
        cudaEventCreateWithFlags(&evJoin, cudaEventDisableTiming);
    }

    // ---- Fork: transform0 on s2 overlaps the CSR build on stream 0 ----
    cudaEventRecord(evFork, 0);
    cudaStreamWaitEvent(s2, evFork, 0);
    transform_mma<64><<<tgrid, 256, smem64, s2>>>(x, Wl0, bl0, Wr0, yp, pp);
    cudaEventRecord(evJoin, s2);

    zero_deg_kernel<<<ngrid, 256>>>();
    deg_kernel<<<e4grid, 256>>>(dst);
    scanA_kernel<<<NB_SCAN, 1024>>>();
    scanC_kernel<<<ngrid, 256>>>();
    fill_kernel<<<e4grid, 256>>>(src, dst);

    // ---- Join, then layer 0 gather ----
    cudaStreamWaitEvent(0, evJoin, 0);
    gather_kernel<64, true, false><<<ggrid, 256>>>(yp, pp, h0p);

    // ---- Layer 1 ----
    transform_mma<64><<<tgrid, 256, smem64>>>(h0p, Wl1, bl1, Wr1, yp, pp);
    gather_kernel<64, true, false><<<ggrid, 256>>>(yp, pp, h1p);

    // ---- Layer 2 (gather fused with log_softmax) ----
    transform_mma<40><<<tgrid, 256, smem40>>>(h1p, Wl2, bl2, Wr2, yp, pp);
    gather_kernel<40, false, true><<<ggrid, 256>>>(yp, pp, out);
}